// round 12
// baseline (speedup 1.0000x reference)
#include <cuda_runtime.h>
#include <cuda_bf16.h>
#include <cstdint>
#include <math.h>

#define BB 2048
#define NN 32
#define HH 256
#define H3 768
#define ZZ 64
#define TB 16
#define NCTA (BB / TB)   // 128
#define AGP 260          // [batch][k] row stride in floats (1040B, 16B-aligned)
#define CHUNK 8
#define NBUF 4
#define NCH (HH / CHUNK)             // 32 chunks per segment
#define WB_FLOATS (CHUNK * H3)       // 6144 floats = 24576 B (2 quads x 768 float4)
#define WB_BYTES  (WB_FLOATS * 4)
#define GC_FLOATS (CHUNK * HH)       // 2048 floats = 8192 B (2 quads x 256 float4)
#define GC_BYTES  (GC_FLOATS * 4)
#define TOTAL_POS (63 * 32)          // interleaved B/C chunk stream

// dynamic smem layout (floats)
#define OFF_WB    0
#define OFF_AGG   (OFF_WB + NBUF * WB_FLOATS)     // 24576
#define OFF_H     (OFF_AGG + TB * AGP)            // +4160
#define OFF_WIH   (OFF_H + TB * AGP)              // +4160
#define OFF_ADJ   (OFF_WIH + 10 * H3)             // +7680
#define OFF_NT    (OFF_ADJ + TB * NN)
#define OFF_MBAR  (OFF_NT + TB)                   // even float count -> 8B aligned
#define SMEM_BYTES ((OFF_MBAR + 16) * 4 + 64)

__device__ float g_gm[BB * NN * HH];      // 64 MB
__device__ float g_adjt[BB * NN * NN];    // 8 MB
// quad-packed transposed weights: [chunk][quad(4k)][column] float4
__device__ float g_whht[HH * H3];         // 196608 floats
__device__ float g_wgt[HH * HH];          // 65536
__device__ float g_wmt[HH * HH];          // 65536

typedef unsigned long long u64;
typedef unsigned int u32;

__device__ __forceinline__ void ffma2(u64 &d, u64 a, u64 b) {
    asm("fma.rn.f32x2 %0, %1, %2, %0;" : "+l"(d) : "l"(a), "l"(b));
}
__device__ __forceinline__ float2 unpack2(u64 a) {
    float2 f; asm("mov.b64 {%0, %1}, %2;" : "=f"(f.x), "=f"(f.y) : "l"(a)); return f;
}
__device__ __forceinline__ float fsig(float x) {
    return __fdividef(1.0f, 1.0f + __expf(-x));
}
__device__ __forceinline__ float ftanh(float x) {
    float y; asm("tanh.approx.f32 %0, %1;" : "=f"(y) : "f"(x)); return y;
}
__device__ __forceinline__ u32 s2u(const void* p) {
    u32 a;
    asm("{ .reg .u64 t; cvta.to.shared.u64 t, %1; cvt.u32.u64 %0, t; }" : "=r"(a) : "l"(p));
    return a;
}
__device__ __forceinline__ void mbar_init(u32 mb, u32 cnt) {
    asm volatile("mbarrier.init.shared.b64 [%0], %1;" :: "r"(mb), "r"(cnt) : "memory");
}
__device__ __forceinline__ void mbar_expect(u32 mb, u32 bytes) {
    asm volatile("mbarrier.arrive.expect_tx.shared.b64 _, [%0], %1;" :: "r"(mb), "r"(bytes) : "memory");
}
__device__ __forceinline__ void mbar_arrive(u32 mb) {
    asm volatile("mbarrier.arrive.release.cta.shared::cta.b64 _, [%0];" :: "r"(mb) : "memory");
}
__device__ __forceinline__ void bulk_cp(u32 dst, const void* src, u32 bytes, u32 mb) {
    asm volatile("cp.async.bulk.shared::cta.global.mbarrier::complete_tx::bytes [%0], [%1], %2, [%3];"
                 :: "r"(dst), "l"(src), "r"(bytes), "r"(mb) : "memory");
}
__device__ __forceinline__ void mbar_wait(u32 mb, u32 parity) {
    asm volatile("{\n\t"
                 ".reg .pred P;\n"
                 "WL%=:\n\t"
                 "mbarrier.try_wait.parity.acquire.cta.shared::cta.b64 P, [%0], %1;\n\t"
                 "@!P bra WL%=;\n\t"
                 "}" :: "r"(mb), "r"(parity) : "memory");
}

__global__ void transpose_adj_kernel(const float* __restrict__ adj) {
    int idx = blockIdx.x * blockDim.x + threadIdx.x;
    if (idx < BB * NN * NN) {
        int b = idx >> 10;
        int r = idx & 1023;
        int v = r >> 5;
        int n = r & 31;
        g_adjt[idx] = adj[(b << 10) + (n << 5) + v];
    }
}

// pack weights into per-chunk quad layout:
//   g_whht[(qq*768 + jj)*4 + i] = w_hh[(qq*4 + i)*H3 + jj]     (qq = k-quad index)
//   g_wgt [(qq*256 + j )*4 + i] = w_gate[(qq*4 + i)*HH + j]
__global__ void prep_weights(const float* __restrict__ w_hh,
                             const float* __restrict__ w_gate,
                             const float* __restrict__ w_map) {
    int idx = blockIdx.x * blockDim.x + threadIdx.x;
    if (idx < HH * H3) {
        int i  = idx & 3;
        int f4 = idx >> 2;
        int jj = f4 % H3;
        int qq = f4 / H3;
        g_whht[idx] = w_hh[(qq * 4 + i) * H3 + jj];
    }
    if (idx < HH * HH) {
        int i  = idx & 3;
        int f4 = idx >> 2;
        int j  = f4 % HH;
        int qq = f4 / HH;
        g_wgt[idx] = w_gate[(qq * 4 + i) * HH + j];
        g_wmt[idx] = w_map[(qq * 4 + i) * HH + j];
    }
}

// issue the TMA copy for global stream position `pos` into buffer (pos & 3)
__device__ __forceinline__ void issue_copy(int pos, u32 wbu, u32 mb_full_base)
{
    const int seg = pos >> 5;
    const int rem = pos & 31;
    const int buf = pos & (NBUF - 1);
    const u32 dst = wbu + (u32)buf * WB_BYTES;
    const u32 mb  = mb_full_base + (u32)buf * 8;
    if (seg & 1) {   // C segment: gate + map chunk
        mbar_expect(mb, 2 * GC_BYTES);
        bulk_cp(dst, g_wgt + rem * GC_FLOATS, GC_BYTES, mb);
        bulk_cp(dst + GC_BYTES, g_wmt + rem * GC_FLOATS, GC_BYTES, mb);
    } else {         // B segment: w_hh chunk
        mbar_expect(mb, WB_BYTES);
        bulk_cp(dst, g_whht + rem * WB_FLOATS, WB_BYTES, mb);
    }
}

__global__ __launch_bounds__(512, 1) void logicvae_main(
    const int*   __restrict__ node_types,
    const float* __restrict__ w_ih,
    const float* __restrict__ b_ih,
    const float* __restrict__ b_hh,
    const float* __restrict__ b_gate,
    const float* __restrict__ w_mu,
    const float* __restrict__ b_mu,
    const float* __restrict__ w_std,
    const float* __restrict__ b_std,
    float* __restrict__ out)
{
    extern __shared__ __align__(128) float smem[];
    float* wb    = smem + OFF_WB;
    float* agg_s = smem + OFF_AGG;    // [batch][AGP]
    float* h_s   = smem + OFF_H;      // [batch][AGP]
    float* wih_s = smem + OFF_WIH;
    float* adj_s = smem + OFF_ADJ;
    int*   nt_s  = (int*)(smem + OFF_NT);

    const u32 wbu      = s2u(wb);
    const u32 mb_full  = s2u(smem + OFF_MBAR);        // 4 full barriers
    const u32 mb_empty = mb_full + NBUF * 8;          // 4 empty barriers

    const int tid = threadIdx.x;       // 0..511
    const int j   = tid & 255;
    const int hb  = (tid >> 8) * 8;
    const int b0  = blockIdx.x * TB;

    const float bihr = b_ih[j], bihz = b_ih[j + HH], bihn = b_ih[j + 2 * HH];
    const float bhhr = b_hh[j], bhhz = b_hh[j + HH], bhhn = b_hh[j + 2 * HH];
    const float bg   = b_gate[j];

    if (tid == 0) {
        #pragma unroll
        for (int i = 0; i < NBUF; i++) {
            mbar_init(mb_full + i * 8, 1);
            mbar_init(mb_empty + i * 8, 512);
        }
    }
    // stage w_ih into smem once (persistent)
    for (int idx = tid; idx < 10 * H3; idx += 512) wih_s[idx] = w_ih[idx];
    __syncthreads();

    // prime ring: stream positions 0..3
    if (tid == 0) {
        #pragma unroll
        for (int p = 0; p < NBUF; p++) issue_copy(p, wbu, mb_full);
    }

    for (int v = 0; v < NN; v++) {
        // ---- adj column v + node types ----
        {
            int b = tid >> 5, n = tid & 31;
            adj_s[tid] = g_adjt[((b0 + b) << 10) + (v << 5) + n];
        }
        if (tid < TB) nt_s[tid] = node_types[(b0 + tid) * NN + v];

        float acc[8];
        #pragma unroll
        for (int b = 0; b < 8; b++) acc[b] = 0.0f;

        __syncthreads();   // BAR 1: adj_s / nt_s

        // ---- Phase A: agg = sum_n adj * gm ----
        for (int n = 0; n < v; n++) {
            float a[8];
            #pragma unroll
            for (int b = 0; b < 8; b++) a[b] = adj_s[(hb + b) * NN + n];
            float s = a[0]+a[1]+a[2]+a[3]+a[4]+a[5]+a[6]+a[7];
            if (s != 0.0f) {
                #pragma unroll
                for (int b = 0; b < 8; b++) {
                    acc[b] = fmaf(a[b],
                                  g_gm[(size_t)((b0 + hb + b) * NN + n) * HH + j],
                                  acc[b]);
                }
            }
        }
        #pragma unroll
        for (int b = 0; b < 8; b++) agg_s[(hb + b) * AGP + j] = acc[b];
        __syncthreads();   // BAR 2: agg_s

        // ---- Phase B: gh = agg @ w_hh, quad-packed weights, k-major pairs ----
        u64 ar2[8], az2[8], an2[8];
        #pragma unroll
        for (int i = 0; i < 8; i++) { ar2[i] = 0ull; az2[i] = 0ull; an2[i] = 0ull; }

        for (int c = 0; c < NCH; c++) {
            const int pos = 64 * v + c;
            const int buf = pos & (NBUF - 1);
            const u32 par = (u32)(pos >> 2) & 1;
            mbar_wait(mb_full + buf * 8, par);
            const float4* W4 = (const float4*)(wb + buf * WB_FLOATS);
            #pragma unroll
            for (int q = 0; q < 2; q++) {
                const int kb = c * CHUNK + q * 4;
                const ulonglong2 wr = *(const ulonglong2*)&W4[q * H3 + j];
                const ulonglong2 wz = *(const ulonglong2*)&W4[q * H3 + HH + j];
                const ulonglong2 wn = *(const ulonglong2*)&W4[q * H3 + 2 * HH + j];
                #pragma unroll
                for (int b = 0; b < 8; b++) {
                    const ulonglong2 A = *(const ulonglong2*)&agg_s[(hb + b) * AGP + kb];
                    ffma2(ar2[b], A.x, wr.x); ffma2(ar2[b], A.y, wr.y);
                    ffma2(az2[b], A.x, wz.x); ffma2(az2[b], A.y, wz.y);
                    ffma2(an2[b], A.x, wn.x); ffma2(an2[b], A.y, wn.y);
                }
            }
            mbar_arrive(mb_empty + buf * 8);
            if (tid == 0 && pos + NBUF < TOTAL_POS) {
                mbar_wait(mb_empty + buf * 8, par);
                issue_copy(pos + NBUF, wbu, mb_full);
            }
        }

        // ---- GRU elementwise (x@w_ih one-hot lookup from smem) ----
        #pragma unroll
        for (int b = 0; b < 8; b++) {
            const int t = nt_s[hb + b];
            const float aggv = agg_s[(hb + b) * AGP + j];
            const float2 fr = unpack2(ar2[b]);
            const float2 fz = unpack2(az2[b]);
            const float2 fn = unpack2(an2[b]);
            const float gir = wih_s[t * H3 + j]          + bihr;
            const float giz = wih_s[t * H3 + HH + j]     + bihz;
            const float gin = wih_s[t * H3 + 2 * HH + j] + bihn;
            const float r   = fsig(gir + (fr.x + fr.y) + bhhr);
            const float z   = fsig(giz + (fz.x + fz.y) + bhhz);
            const float nn_ = ftanh(gin + r * ((fn.x + fn.y) + bhhn));
            h_s[(hb + b) * AGP + j] = (1.0f - z) * nn_ + z * aggv;
        }
        __syncthreads();   // BAR 3: h_s

        if (v < NN - 1) {
            // ---- Phase C: gm_v = sigmoid(h@w_gate+bg) * (h@w_map) ----
            u64 ag2[8], am2[8];
            #pragma unroll
            for (int i = 0; i < 8; i++) { ag2[i] = 0ull; am2[i] = 0ull; }

            for (int c = 0; c < NCH; c++) {
                const int pos = 64 * v + 32 + c;
                const int buf = pos & (NBUF - 1);
                const u32 par = (u32)(pos >> 2) & 1;
                mbar_wait(mb_full + buf * 8, par);
                const float4* G4 = (const float4*)(wb + buf * WB_FLOATS);
                const float4* M4 = (const float4*)(wb + buf * WB_FLOATS + GC_FLOATS);
                #pragma unroll
                for (int q = 0; q < 2; q++) {
                    const int kb = c * CHUNK + q * 4;
                    const ulonglong2 wg = *(const ulonglong2*)&G4[q * HH + j];
                    const ulonglong2 wm = *(const ulonglong2*)&M4[q * HH + j];
                    #pragma unroll
                    for (int b = 0; b < 8; b++) {
                        const ulonglong2 Hh = *(const ulonglong2*)&h_s[(hb + b) * AGP + kb];
                        ffma2(ag2[b], Hh.x, wg.x); ffma2(ag2[b], Hh.y, wg.y);
                        ffma2(am2[b], Hh.x, wm.x); ffma2(am2[b], Hh.y, wm.y);
                    }
                }
                mbar_arrive(mb_empty + buf * 8);
                if (tid == 0 && pos + NBUF < TOTAL_POS) {
                    mbar_wait(mb_empty + buf * 8, par);
                    issue_copy(pos + NBUF, wbu, mb_full);
                }
            }

            #pragma unroll
            for (int b = 0; b < 8; b++) {
                const float2 fg = unpack2(ag2[b]);
                const float2 fm = unpack2(am2[b]);
                g_gm[(size_t)((b0 + hb + b) * NN + v) * HH + j] =
                    fsig((fg.x + fg.y) + bg) * (fm.x + fm.y);
            }
        } else {
            // ---- Final: mu = h31@w_mu+b_mu ; sigma = h31@w_std+b_std ----
            const int z   = tid & 63;
            const int grp = tid >> 6;
            const int bA  = 2 * grp, bB = 2 * grp + 1;
            float am0 = 0.f, am1 = 0.f, as0 = 0.f, as1 = 0.f;
            #pragma unroll 4
            for (int k = 0; k < HH; k++) {
                const float wm = w_mu[k * ZZ + z];
                const float ws = w_std[k * ZZ + z];
                const float h0 = h_s[bA * AGP + k];
                const float h1 = h_s[bB * AGP + k];
                am0 = fmaf(h0, wm, am0); am1 = fmaf(h1, wm, am1);
                as0 = fmaf(h0, ws, as0); as1 = fmaf(h1, ws, as1);
            }
            const float bmu = b_mu[z], bstd = b_std[z];
            out[(size_t)(b0 + bA) * ZZ + z] = am0 + bmu;
            out[(size_t)(b0 + bB) * ZZ + z] = am1 + bmu;
            out[(size_t)BB * ZZ + (size_t)(b0 + bA) * ZZ + z] = as0 + bstd;
            out[(size_t)BB * ZZ + (size_t)(b0 + bB) * ZZ + z] = as1 + bstd;
        }
    }
}

extern "C" void kernel_launch(void* const* d_in, const int* in_sizes, int n_in,
                              void* d_out, int out_size) {
    const float* adj        = (const float*)d_in[0];
    const int*   node_types = (const int*)  d_in[1];
    const float* w_ih       = (const float*)d_in[2];
    const float* w_hh       = (const float*)d_in[3];
    const float* b_ih       = (const float*)d_in[4];
    const float* b_hh       = (const float*)d_in[5];
    const float* w_gate     = (const float*)d_in[6];
    const float* b_gate     = (const float*)d_in[7];
    const float* w_map      = (const float*)d_in[8];
    const float* w_mu       = (const float*)d_in[9];
    const float* b_mu       = (const float*)d_in[10];
    const float* w_std      = (const float*)d_in[11];
    const float* b_std      = (const float*)d_in[12];
    float* out = (float*)d_out;

    cudaFuncSetAttribute(logicvae_main,
                         cudaFuncAttributeMaxDynamicSharedMemorySize, SMEM_BYTES);

    transpose_adj_kernel<<<(BB * NN * NN + 255) / 256, 256>>>(adj);
    prep_weights<<<(HH * H3 + 255) / 256, 256>>>(w_hh, w_gate, w_map);

    logicvae_main<<<NCTA, 512, SMEM_BYTES>>>(node_types, w_ih, b_ih, b_hh,
                                             b_gate, w_mu, b_mu, w_std, b_std, out);
}

// round 13
// speedup vs baseline: 1.8960x; 1.8960x over previous
#include <cuda_runtime.h>
#include <cuda_bf16.h>
#include <cstdint>
#include <math.h>

#define BB 2048
#define NN 32
#define HH 256
#define H3 768
#define ZZ 64
#define TB 16
#define NCTA (BB / TB)   // 128
#define PAD 20
#define CHUNK 16
#define NBUF 3
#define NCH (HH / CHUNK)             // 16 chunks per segment
#define WB_FLOATS (CHUNK * H3)       // 12288 floats = 49152 B
#define WB_BYTES  (WB_FLOATS * 4)
#define GC_FLOATS (CHUNK * HH)       // 4096 floats = 16384 B
#define GC_BYTES  (GC_FLOATS * 4)
#define TOTAL_POS (63 * 16)          // interleaved B/C chunk stream (16 chunks/segment)

// dynamic smem layout (floats)
#define OFF_WB    0
#define OFF_AGG   (OFF_WB + NBUF * WB_FLOATS)     // 36864
#define OFF_H     (OFF_AGG + HH * PAD)
#define OFF_WIH   (OFF_H + HH * PAD)
#define OFF_ADJ   (OFF_WIH + 10 * H3)
#define OFF_NT    (OFF_ADJ + TB * NN)
#define OFF_MBAR  (OFF_NT + TB)                   // even float count -> 8B aligned
#define SMEM_BYTES ((OFF_MBAR + 16) * 4 + 64)     // ~216 KB

__device__ float g_gm[BB * NN * HH];      // 64 MB
__device__ float g_adjt[BB * NN * NN];    // 8 MB

typedef unsigned long long u64;
typedef unsigned int u32;

__device__ __forceinline__ u64 pack2(float x) {
    u64 r; asm("mov.b64 %0, {%1, %1};" : "=l"(r) : "f"(x)); return r;
}
__device__ __forceinline__ void ffma2(u64 &d, u64 a, u64 b) {
    asm("fma.rn.f32x2 %0, %1, %2, %0;" : "+l"(d) : "l"(a), "l"(b));
}
__device__ __forceinline__ float2 unpack2(u64 a) {
    float2 f; asm("mov.b64 {%0, %1}, %2;" : "=f"(f.x), "=f"(f.y) : "l"(a)); return f;
}
__device__ __forceinline__ float fsig(float x) {
    return __fdividef(1.0f, 1.0f + __expf(-x));
}
__device__ __forceinline__ float ftanh(float x) {
    float y; asm("tanh.approx.f32 %0, %1;" : "=f"(y) : "f"(x)); return y;
}
__device__ __forceinline__ u32 s2u(const void* p) {
    u32 a;
    asm("{ .reg .u64 t; cvta.to.shared.u64 t, %1; cvt.u32.u64 %0, t; }" : "=r"(a) : "l"(p));
    return a;
}
__device__ __forceinline__ void mbar_init(u32 mb, u32 cnt) {
    asm volatile("mbarrier.init.shared.b64 [%0], %1;" :: "r"(mb), "r"(cnt) : "memory");
}
__device__ __forceinline__ void mbar_expect(u32 mb, u32 bytes) {
    asm volatile("mbarrier.arrive.expect_tx.shared.b64 _, [%0], %1;" :: "r"(mb), "r"(bytes) : "memory");
}
__device__ __forceinline__ void mbar_arrive(u32 mb) {
    asm volatile("mbarrier.arrive.release.cta.shared::cta.b64 _, [%0];" :: "r"(mb) : "memory");
}
__device__ __forceinline__ void bulk_cp(u32 dst, const void* src, u32 bytes, u32 mb) {
    asm volatile("cp.async.bulk.shared::cta.global.mbarrier::complete_tx::bytes [%0], [%1], %2, [%3];"
                 :: "r"(dst), "l"(src), "r"(bytes), "r"(mb) : "memory");
}
__device__ __forceinline__ void mbar_wait(u32 mb, u32 parity) {
    asm volatile("{\n\t"
                 ".reg .pred P;\n"
                 "WL%=:\n\t"
                 "mbarrier.try_wait.parity.acquire.cta.shared::cta.b64 P, [%0], %1;\n\t"
                 "@!P bra WL%=;\n\t"
                 "}" :: "r"(mb), "r"(parity) : "memory");
}

__global__ void transpose_adj_kernel(const float* __restrict__ adj) {
    int idx = blockIdx.x * blockDim.x + threadIdx.x;
    if (idx < BB * NN * NN) {
        int b = idx >> 10;
        int r = idx & 1023;
        int v = r >> 5;
        int n = r & 31;
        g_adjt[idx] = adj[(b << 10) + (n << 5) + v];
    }
}

// issue the TMA copy for global stream position `pos` into buffer `buf`
__device__ __forceinline__ void issue_copy(
    int pos, int buf, u32 wbu, u32 mb_full_base,
    const float* __restrict__ w_hh,
    const float* __restrict__ w_gate,
    const float* __restrict__ w_map)
{
    const int seg = pos >> 4;            // 16 chunks per segment
    const int rem = pos & 15;
    const u32 dst = wbu + (u32)buf * WB_BYTES;
    const u32 mb  = mb_full_base + (u32)buf * 8;
    if (seg & 1) {   // C segment: gate + map chunk
        mbar_expect(mb, 2 * GC_BYTES);
        bulk_cp(dst, w_gate + rem * GC_FLOATS, GC_BYTES, mb);
        bulk_cp(dst + GC_BYTES, w_map + rem * GC_FLOATS, GC_BYTES, mb);
    } else {         // B segment: w_hh chunk
        mbar_expect(mb, WB_BYTES);
        bulk_cp(dst, w_hh + rem * WB_FLOATS, WB_BYTES, mb);
    }
}

__global__ __launch_bounds__(512, 1) void logicvae_main(
    const int*   __restrict__ node_types,
    const float* __restrict__ w_ih,
    const float* __restrict__ w_hh,
    const float* __restrict__ b_ih,
    const float* __restrict__ b_hh,
    const float* __restrict__ w_gate,
    const float* __restrict__ b_gate,
    const float* __restrict__ w_map,
    const float* __restrict__ w_mu,
    const float* __restrict__ b_mu,
    const float* __restrict__ w_std,
    const float* __restrict__ b_std,
    float* __restrict__ out)
{
    extern __shared__ __align__(128) float smem[];
    float* wb    = smem + OFF_WB;
    float* agg_s = smem + OFF_AGG;
    float* h_s   = smem + OFF_H;
    float* wih_s = smem + OFF_WIH;
    float* adj_s = smem + OFF_ADJ;
    int*   nt_s  = (int*)(smem + OFF_NT);

    const u32 wbu      = s2u(wb);
    const u32 mb_full  = s2u(smem + OFF_MBAR);        // 3 full barriers
    const u32 mb_empty = mb_full + NBUF * 8;          // 3 empty barriers

    const int tid = threadIdx.x;       // 0..511
    const int j   = tid & 255;
    const int hb  = (tid >> 8) * 8;
    const int b0  = blockIdx.x * TB;

    const float bihr = b_ih[j], bihz = b_ih[j + HH], bihn = b_ih[j + 2 * HH];
    const float bhhr = b_hh[j], bhhz = b_hh[j + HH], bhhn = b_hh[j + 2 * HH];
    const float bg   = b_gate[j];

    if (tid == 0) {
        #pragma unroll
        for (int i = 0; i < NBUF; i++) {
            mbar_init(mb_full + i * 8, 1);
            mbar_init(mb_empty + i * 8, 512);
        }
    }
    // stage w_ih into smem once (persistent)
    for (int idx = tid; idx < 10 * H3; idx += 512) wih_s[idx] = w_ih[idx];
    __syncthreads();

    // prime ring: stream positions 0..NBUF-1 into buffers 0..NBUF-1
    if (tid == 0) {
        #pragma unroll
        for (int p = 0; p < NBUF; p++) issue_copy(p, p, wbu, mb_full, w_hh, w_gate, w_map);
    }

    // round-robin ring cursor, uniform across all threads:
    // buf = pos % NBUF, par = (pos / NBUF) & 1
    int cur_buf = 0;
    u32 cur_par = 0;
    int cur_pos = 0;

    for (int v = 0; v < NN; v++) {
        // ---- adj column v + node types ----
        {
            int b = tid >> 5, n = tid & 31;
            adj_s[tid] = g_adjt[((b0 + b) << 10) + (v << 5) + n];
        }
        if (tid < TB) nt_s[tid] = node_types[(b0 + tid) * NN + v];

        float acc[8];
        #pragma unroll
        for (int b = 0; b < 8; b++) acc[b] = 0.0f;

        __syncthreads();   // BAR 1: adj_s / nt_s

        // ---- Phase A: agg = sum_n adj * gm ----
        for (int n = 0; n < v; n++) {
            float a[8];
            #pragma unroll
            for (int b = 0; b < 8; b++) a[b] = adj_s[(hb + b) * NN + n];
            float s = a[0]+a[1]+a[2]+a[3]+a[4]+a[5]+a[6]+a[7];
            if (s != 0.0f) {
                #pragma unroll
                for (int b = 0; b < 8; b++) {
                    acc[b] = fmaf(a[b],
                                  g_gm[(size_t)((b0 + hb + b) * NN + n) * HH + j],
                                  acc[b]);
                }
            }
        }
        {
            float4* a4 = (float4*)(agg_s + j * PAD + hb);
            a4[0] = make_float4(acc[0], acc[1], acc[2], acc[3]);
            a4[1] = make_float4(acc[4], acc[5], acc[6], acc[7]);
        }
        __syncthreads();   // BAR 2: agg_s

        // ---- Phase B: gh = agg @ w_hh, ring-streamed weights ----
        u64 ar2[4], az2[4], an2[4];
        #pragma unroll
        for (int i = 0; i < 4; i++) { ar2[i] = 0ull; az2[i] = 0ull; an2[i] = 0ull; }

        for (int c = 0; c < NCH; c++) {
            const int buf = cur_buf;
            const u32 par = cur_par;
            mbar_wait(mb_full + buf * 8, par);
            const float* W = wb + buf * WB_FLOATS;
            #pragma unroll 8
            for (int kk = 0; kk < CHUNK; kk++) {
                const int k = c * CHUNK + kk;
                const u64 wr2 = pack2(W[kk * H3 + j]);
                const u64 wz2 = pack2(W[kk * H3 + HH + j]);
                const u64 wn2 = pack2(W[kk * H3 + 2 * HH + j]);
                const ulonglong2* p = (const ulonglong2*)(agg_s + k * PAD + hb);
                const ulonglong2 q0 = p[0], q1 = p[1];
                ffma2(ar2[0], q0.x, wr2); ffma2(ar2[1], q0.y, wr2);
                ffma2(ar2[2], q1.x, wr2); ffma2(ar2[3], q1.y, wr2);
                ffma2(az2[0], q0.x, wz2); ffma2(az2[1], q0.y, wz2);
                ffma2(az2[2], q1.x, wz2); ffma2(az2[3], q1.y, wz2);
                ffma2(an2[0], q0.x, wn2); ffma2(an2[1], q0.y, wn2);
                ffma2(an2[2], q1.x, wn2); ffma2(an2[3], q1.y, wn2);
            }
            mbar_arrive(mb_empty + buf * 8);
            if (tid == 0 && cur_pos + NBUF < TOTAL_POS) {
                mbar_wait(mb_empty + buf * 8, par);
                issue_copy(cur_pos + NBUF, buf, wbu, mb_full, w_hh, w_gate, w_map);
            }
            cur_pos++;
            if (++cur_buf == NBUF) { cur_buf = 0; cur_par ^= 1; }
        }

        // ---- GRU elementwise (x@w_ih one-hot lookup from smem) ----
        {
            float hval[8];
            #pragma unroll
            for (int i = 0; i < 4; i++) {
                const float2 fr = unpack2(ar2[i]);
                const float2 fz = unpack2(az2[i]);
                const float2 fn = unpack2(an2[i]);
                #pragma unroll
                for (int u = 0; u < 2; u++) {
                    const int b = 2 * i + u;
                    const int t = nt_s[hb + b];
                    const float gir = wih_s[t * H3 + j]          + bihr;
                    const float giz = wih_s[t * H3 + HH + j]     + bihz;
                    const float gin = wih_s[t * H3 + 2 * HH + j] + bihn;
                    const float arv = u ? fr.y : fr.x;
                    const float azv = u ? fz.y : fz.x;
                    const float anv = u ? fn.y : fn.x;
                    const float r   = fsig(gir + arv + bhhr);
                    const float z   = fsig(giz + azv + bhhz);
                    const float nn_ = ftanh(gin + r * (anv + bhhn));
                    hval[b] = (1.0f - z) * nn_ + z * acc[b];
                }
            }
            float4* h4w = (float4*)(h_s + j * PAD + hb);
            h4w[0] = make_float4(hval[0], hval[1], hval[2], hval[3]);
            h4w[1] = make_float4(hval[4], hval[5], hval[6], hval[7]);
        }
        __syncthreads();   // BAR 3: h_s

        if (v < NN - 1) {
            // ---- Phase C: gm_v = sigmoid(h@w_gate+bg) * (h@w_map) ----
            u64 ag2[4], am2[4];
            #pragma unroll
            for (int i = 0; i < 4; i++) { ag2[i] = 0ull; am2[i] = 0ull; }

            for (int c = 0; c < NCH; c++) {
                const int buf = cur_buf;
                const u32 par = cur_par;
                mbar_wait(mb_full + buf * 8, par);
                const float* W = wb + buf * WB_FLOATS;
                #pragma unroll 8
                for (int kk = 0; kk < CHUNK; kk++) {
                    const int k = c * CHUNK + kk;
                    const u64 wg2 = pack2(W[kk * HH + j]);
                    const u64 wm2 = pack2(W[GC_FLOATS + kk * HH + j]);
                    const ulonglong2* p = (const ulonglong2*)(h_s + k * PAD + hb);
                    const ulonglong2 q0 = p[0], q1 = p[1];
                    ffma2(ag2[0], q0.x, wg2); ffma2(ag2[1], q0.y, wg2);
                    ffma2(ag2[2], q1.x, wg2); ffma2(ag2[3], q1.y, wg2);
                    ffma2(am2[0], q0.x, wm2); ffma2(am2[1], q0.y, wm2);
                    ffma2(am2[2], q1.x, wm2); ffma2(am2[3], q1.y, wm2);
                }
                mbar_arrive(mb_empty + buf * 8);
                if (tid == 0 && cur_pos + NBUF < TOTAL_POS) {
                    mbar_wait(mb_empty + buf * 8, par);
                    issue_copy(cur_pos + NBUF, buf, wbu, mb_full, w_hh, w_gate, w_map);
                }
                cur_pos++;
                if (++cur_buf == NBUF) { cur_buf = 0; cur_par ^= 1; }
            }

            #pragma unroll
            for (int i = 0; i < 4; i++) {
                const float2 fg = unpack2(ag2[i]);
                const float2 fm = unpack2(am2[i]);
                const int ba = hb + 2 * i;
                g_gm[(size_t)((b0 + ba)     * NN + v) * HH + j] = fsig(fg.x + bg) * fm.x;
                g_gm[(size_t)((b0 + ba + 1) * NN + v) * HH + j] = fsig(fg.y + bg) * fm.y;
            }
        } else {
            // ---- Final: mu = h31@w_mu+b_mu ; sigma = h31@w_std+b_std ----
            const int z   = tid & 63;
            const int grp = tid >> 6;
            const int bA  = 2 * grp, bB = 2 * grp + 1;
            float am0 = 0.f, am1 = 0.f, as0 = 0.f, as1 = 0.f;
            #pragma unroll 4
            for (int k = 0; k < HH; k++) {
                const float wm = w_mu[k * ZZ + z];
                const float ws = w_std[k * ZZ + z];
                const float h0 = h_s[k * PAD + bA];
                const float h1 = h_s[k * PAD + bB];
                am0 = fmaf(h0, wm, am0); am1 = fmaf(h1, wm, am1);
                as0 = fmaf(h0, ws, as0); as1 = fmaf(h1, ws, as1);
            }
            const float bmu = b_mu[z], bstd = b_std[z];
            out[(size_t)(b0 + bA) * ZZ + z] = am0 + bmu;
            out[(size_t)(b0 + bB) * ZZ + z] = am1 + bmu;
            out[(size_t)BB * ZZ + (size_t)(b0 + bA) * ZZ + z] = as0 + bstd;
            out[(size_t)BB * ZZ + (size_t)(b0 + bB) * ZZ + z] = as1 + bstd;
        }
    }
}

extern "C" void kernel_launch(void* const* d_in, const int* in_sizes, int n_in,
                              void* d_out, int out_size) {
    const float* adj        = (const float*)d_in[0];
    const int*   node_types = (const int*)  d_in[1];
    const float* w_ih       = (const float*)d_in[2];
    const float* w_hh       = (const float*)d_in[3];
    const float* b_ih       = (const float*)d_in[4];
    const float* b_hh       = (const float*)d_in[5];
    const float* w_gate     = (const float*)d_in[6];
    const float* b_gate     = (const float*)d_in[7];
    const float* w_map      = (const float*)d_in[8];
    const float* w_mu       = (const float*)d_in[9];
    const float* b_mu       = (const float*)d_in[10];
    const float* w_std      = (const float*)d_in[11];
    const float* b_std      = (const float*)d_in[12];
    float* out = (float*)d_out;

    cudaFuncSetAttribute(logicvae_main,
                         cudaFuncAttributeMaxDynamicSharedMemorySize, SMEM_BYTES);

    transpose_adj_kernel<<<(BB * NN * NN + 255) / 256, 256>>>(adj);

    logicvae_main<<<NCTA, 512, SMEM_BYTES>>>(node_types, w_ih, w_hh, b_ih, b_hh,
                                             w_gate, b_gate, w_map,
                                             w_mu, b_mu, w_std, b_std, out);
}